// round 4
// baseline (speedup 1.0000x reference)
#include <cuda_runtime.h>
#include <cuda_bf16.h>
#include <math.h>

#define T_ 512
#define B_ 64
#define I_ 128
#define H_ 512
#define O_ 128
#define K_ 32
#define N3 1536
#define IH 640
#define NCTA 128

typedef unsigned long long u64;

// ---------------- device scratch (allocation-free rule) ----------------
__device__ float g_XP[(size_t)T_ * B_ * N3];          // x-projection + bias  [t][b][h*3+g]
__device__ float g_Hall[(size_t)(T_ + 1) * B_ * H_];  // h_0..h_T  [t][b][h]
__device__ float g_WxP[I_ * N3];                      // [k][h*3+g]
__device__ float g_WhP[H_ * N3];                      // [ng][k 512][hloc*3+g]  (32*512*48)
__device__ float g_bn[N3];                            // [h*3+g]
__device__ float g_wd[K_ * H_];                       // [j][h], oldest lag first
__device__ unsigned g_count;
__device__ unsigned g_gen;

// ---------------- f32x2 helpers ----------------
__device__ __forceinline__ void fma2(u64 &d, u64 a, u64 b) {
    asm("fma.rn.f32x2 %0, %1, %2, %0;" : "+l"(d) : "l"(a), "l"(b));
}
__device__ __forceinline__ u64 dup2(float w) {
    u64 r; asm("mov.b64 %0, {%1, %1};" : "=l"(r) : "f"(w)); return r;
}
__device__ __forceinline__ float2 unpack2(u64 v) {
    float2 f; asm("mov.b64 {%0, %1}, %2;" : "=f"(f.x), "=f"(f.y) : "l"(v)); return f;
}
__device__ __forceinline__ float sigmoidf_(float x) { return 1.f / (1.f + expf(-x)); }

// ---------------- prep: pack weights/biases/frac-diff weights, zero h_0, reset barrier ----
__global__ void prep_kernel(const float *__restrict__ Wi, const float *__restrict__ bi,
                            const float *__restrict__ Wo, const float *__restrict__ bo,
                            const float *__restrict__ Wc, const float *__restrict__ bc,
                            const float *__restrict__ dv) {
    int idx = blockIdx.x * blockDim.x + threadIdx.x;
    if (idx == 0) { g_count = 0u; g_gen = 0u; }
    if (idx < IH * H_) {
        int k = idx >> 9, h = idx & 511;
        float wi = Wi[idx], wo = Wo[idx], wc = Wc[idx];
        if (k < I_) {
            float *p = g_WxP + (size_t)k * N3 + h * 3;
            p[0] = wi; p[1] = wo; p[2] = wc;
        } else {
            int kk = k - I_;
            float *p = g_WhP + (size_t)(h >> 4) * (512 * 48) + (size_t)kk * 48 + (h & 15) * 3;
            p[0] = wi; p[1] = wo; p[2] = wc;
        }
    }
    if (idx < H_) {
        g_bn[idx * 3 + 0] = bi[idx];
        g_bn[idx * 3 + 1] = bo[idx];
        g_bn[idx * 3 + 2] = bc[idx];
        float d = 0.5f * sigmoidf_(dv[idx]);
        float v = 1.f;
        for (int i = 0; i < K_; i++) {          // v_{i+1} = v_i*(i-d)/(i+1); wd[K-1-i]=v_{i+1}
            v *= ((float)i - d) / ((float)i + 1.f);
            g_wd[(K_ - 1 - i) * H_ + idx] = v;
        }
    }
    if (idx < B_ * H_) g_Hall[idx] = 0.f;       // h_0 = 0
}

// ---------------- generic fp32 GEMM + bias: C[M,N] = A[M,Kd] @ Bm[Kd,N] + bias[N] --------
// BM=64 BN=64 BK=16, 256 threads, 4m x 4n micro-tile via f32x2 over m-pairs.
__global__ void __launch_bounds__(256) gemm_bias(const float *__restrict__ A,
                                                 const float *__restrict__ Bm,
                                                 const float *__restrict__ bias,
                                                 float *__restrict__ C, int N, int Kd) {
    __shared__ float As[16 * 64];   // [k][mpair*2+comp]
    __shared__ u64   Bs[16 * 64];   // [k][n], dup'd
    int tid = threadIdx.x;
    int m0 = blockIdx.x * 64, n0 = blockIdx.y * 64;
    int tx = tid & 15, ty = tid >> 4;
    int ar = tid >> 2, ac = (tid & 3) * 4;
    int bk = tid >> 4, bn = (tid & 15) * 4;

    u64 acc[2][4];
#pragma unroll
    for (int p = 0; p < 2; p++)
#pragma unroll
        for (int i = 0; i < 4; i++) acc[p][i] = 0ull;

    for (int kc = 0; kc < Kd; kc += 16) {
        float4 av = *(const float4 *)(A + (size_t)(m0 + ar) * Kd + kc + ac);
        float4 bv = *(const float4 *)(Bm + (size_t)(kc + bk) * N + n0 + bn);
        __syncthreads();
        float avs[4] = {av.x, av.y, av.z, av.w};
#pragma unroll
        for (int q = 0; q < 4; q++) As[((ac + q) * 32 + (ar >> 1)) * 2 + (ar & 1)] = avs[q];
        float bvs[4] = {bv.x, bv.y, bv.z, bv.w};
#pragma unroll
        for (int q = 0; q < 4; q++) Bs[bk * 64 + bn + q] = dup2(bvs[q]);
        __syncthreads();
#pragma unroll
        for (int kk = 0; kk < 16; kk++) {
            u64 a0 = *(const u64 *)&As[(kk * 32 + ty * 2 + 0) * 2];
            u64 a1 = *(const u64 *)&As[(kk * 32 + ty * 2 + 1) * 2];
            u64 b0 = Bs[kk * 64 + tx], b1 = Bs[kk * 64 + tx + 16];
            u64 b2 = Bs[kk * 64 + tx + 32], b3 = Bs[kk * 64 + tx + 48];
            fma2(acc[0][0], a0, b0); fma2(acc[0][1], a0, b1);
            fma2(acc[0][2], a0, b2); fma2(acc[0][3], a0, b3);
            fma2(acc[1][0], a1, b0); fma2(acc[1][1], a1, b1);
            fma2(acc[1][2], a1, b2); fma2(acc[1][3], a1, b3);
        }
    }
#pragma unroll
    for (int p = 0; p < 2; p++) {
        int m = m0 + ty * 4 + p * 2;
#pragma unroll
        for (int i = 0; i < 4; i++) {
            int n = n0 + tx + 16 * i;
            float2 v = unpack2(acc[p][i]);
            float bb = bias[n];
            C[(size_t)m * N + n] = v.x + bb;
            C[(size_t)(m + 1) * N + n] = v.y + bb;
        }
    }
}

// ---------------- persistent recurrent kernel: 128 CTAs = 4 bg x 32 ng ----------------
// SMEM floats: Whs[0,24576)  h2s[24576,33792) (512x9 u64)  ring[33792,41984)
//              red[41984,48128) (3072 u64)  wds[48128,48640)
#define SMEM_FLOATS 48640
#define SMEM_BYTES (SMEM_FLOATS * 4)

__global__ void __launch_bounds__(256, 1) recurrent_kernel(float *__restrict__ dout) {
    extern __shared__ float sm[];
    float *Whs = sm;
    u64 *h2s = (u64 *)(sm + 24576);
    float *h2f = sm + 24576;
    float *ring = sm + 33792;
    u64 *red = (u64 *)(sm + 41984);
    const float *redf = sm + 41984;
    float *wds = sm + 48128;

    int tid = threadIdx.x;
    int bid = blockIdx.x;
    int bg = bid >> 5, ng = bid & 31;
    int bbase = bg * 16, hbase = ng * 16;

    // load weight slice [512][48] (coalesced float4)
    {
        const float4 *src = (const float4 *)(g_WhP + (size_t)ng * (512 * 48));
        float4 *dst = (float4 *)Whs;
        for (int i = tid; i < 512 * 48 / 4; i += 256) dst[i] = src[i];
    }
    for (int i = tid; i < K_ * 16; i += 256)
        wds[i] = g_wd[(i >> 4) * H_ + hbase + (i & 15)];
    for (int i = tid; i < K_ * 256; i += 256) ring[i] = 0.f;
    __syncthreads();

    // GEMM role
    int ks = tid >> 5, lane = tid & 31;
    int bpH = lane >> 4, hq = lane & 15;
    int kbase = ks * 64;
    // elementwise role
    int h_l = tid & 15, b_l = tid >> 4;
    int bp = b_l >> 1, comp = b_l & 1;
    // stage role
    int sb = tid >> 4, sk = (tid & 15) * 32;

    for (int t = 0; t < T_; t++) {
        // prefetch x-projection for this thread's (b,h)
        const float *xpp = g_XP + ((size_t)t * B_ + bbase + b_l) * N3 + (size_t)(hbase + h_l) * 3;
        float xp0 = xpp[0], xp1 = xpp[1], xp2 = xpp[2];

        // stage h_t slice [16b][512] -> [k][bp] pairs
        {
            const float4 *src = (const float4 *)(g_Hall + (size_t)t * (B_ * H_) +
                                                 (size_t)(bbase + sb) * H_ + sk);
            int bcol = (sb >> 1) * 2 + (sb & 1);
#pragma unroll
            for (int q = 0; q < 8; q++) {
                float4 v = src[q];
                int k = sk + q * 4;
                h2f[(k + 0) * 18 + bcol] = v.x;
                h2f[(k + 1) * 18 + bcol] = v.y;
                h2f[(k + 2) * 18 + bcol] = v.z;
                h2f[(k + 3) * 18 + bcol] = v.w;
            }
        }
        __syncthreads();

        // GEMM partials: k in [kbase,kbase+64), outputs (4 bp, 1 h, 3 gates)
        u64 a00 = 0, a01 = 0, a02 = 0, a10 = 0, a11 = 0, a12 = 0;
        u64 a20 = 0, a21 = 0, a22 = 0, a30 = 0, a31 = 0, a32 = 0;
        {
            const u64 *hr = h2s + (size_t)kbase * 9 + bpH * 4;
            const float *wr = Whs + kbase * 48 + hq * 3;
#pragma unroll 4
            for (int k = 0; k < 64; k++) {
                u64 h0 = hr[0], h1 = hr[1], h2v = hr[2], h3v = hr[3];
                u64 w0 = dup2(wr[0]), w1 = dup2(wr[1]), w2 = dup2(wr[2]);
                fma2(a00, h0, w0);  fma2(a01, h0, w1);  fma2(a02, h0, w2);
                fma2(a10, h1, w0);  fma2(a11, h1, w1);  fma2(a12, h1, w2);
                fma2(a20, h2v, w0); fma2(a21, h2v, w1); fma2(a22, h2v, w2);
                fma2(a30, h3v, w0); fma2(a31, h3v, w1); fma2(a32, h3v, w2);
                hr += 9; wr += 48;
            }
        }
        {
            u64 *rp = red + ((size_t)(ks * 8 + bpH * 4) * 16 + hq) * 3;
            rp[0] = a00;  rp[1] = a01;  rp[2] = a02;
            rp[48] = a10; rp[49] = a11; rp[50] = a12;
            rp[96] = a20; rp[97] = a21; rp[98] = a22;
            rp[144] = a30; rp[145] = a31; rp[146] = a32;
        }
        __syncthreads();

        // elementwise per (b_l,h_l): reduce k-splits, gates, frac-diff, update
        float p0 = xp0, p1 = xp1, p2 = xp2;
#pragma unroll
        for (int s = 0; s < 8; s++) {
            int base = (((s * 8 + bp) * 16 + h_l) * 3) * 2 + comp;
            p0 += redf[base];
            p1 += redf[base + 2];
            p2 += redf[base + 4];
        }
        float gi = sigmoidf_(p0);
        float go = sigmoidf_(p1);
        float gc = tanhf(p2);
        float conv = 0.f;
        int rbase = b_l * 16 + h_l;
#pragma unroll
        for (int j = 0; j < K_; j++)
            conv += wds[j * 16 + h_l] * ring[(((t + j) & 31) << 8) + rbase];
        float c = gi * gc - conv;
        ring[((t & 31) << 8) + rbase] = c;   // only this thread reads/writes this slot
        float hn = go * tanhf(c);
        g_Hall[((size_t)(t + 1) * B_ + bbase + b_l) * H_ + hbase + h_l] = hn;
        if (t == T_ - 1)
            dout[(size_t)T_ * B_ * O_ + (size_t)(bbase + b_l) * H_ + hbase + h_l] = hn;

        // ---- grid barrier (monotonic count + generation) ----
        __syncthreads();
        if (tid == 0) {
            __threadfence();
            unsigned arrived = atomicAdd(&g_count, 1u) + 1u;
            unsigned target = (unsigned)(NCTA * (t + 1));
            if (arrived == target) {
                atomicExch(&g_gen, (unsigned)(t + 1));
            } else {
                while (*((volatile unsigned *)&g_gen) < (unsigned)(t + 1)) __nanosleep(64);
            }
            __threadfence();
        }
        __syncthreads();
    }

    // epilogue: hc_last = ring (slot j == hc_last[j] since 480 % 32 == 0)
    {
        const size_t HC0 = (size_t)T_ * B_ * O_ + (size_t)B_ * H_;
#pragma unroll
        for (int j = 0; j < K_; j++)
            dout[HC0 + ((size_t)j * B_ + bbase + b_l) * H_ + hbase + h_l] =
                ring[(j << 8) + b_l * 16 + h_l];
    }
}

// ---------------- launch ----------------
extern "C" void kernel_launch(void* const* d_in, const int* in_sizes, int n_in,
                              void* d_out, int out_size) {
    const float *inputs = (const float *)d_in[0];
    const float *Wi = (const float *)d_in[1];
    const float *bi = (const float *)d_in[2];
    const float *Wo = (const float *)d_in[3];
    const float *bo = (const float *)d_in[4];
    const float *Wc = (const float *)d_in[5];
    const float *bc = (const float *)d_in[6];
    const float *Wout = (const float *)d_in[7];
    const float *bout = (const float *)d_in[8];
    const float *dv = (const float *)d_in[9];
    float *out = (float *)d_out;

    float *pXP = nullptr, *pHall = nullptr, *pWxP = nullptr, *pBn = nullptr;
    cudaGetSymbolAddress((void **)&pXP, g_XP);
    cudaGetSymbolAddress((void **)&pHall, g_Hall);
    cudaGetSymbolAddress((void **)&pWxP, g_WxP);
    cudaGetSymbolAddress((void **)&pBn, g_bn);
    cudaFuncSetAttribute(recurrent_kernel, cudaFuncAttributeMaxDynamicSharedMemorySize,
                         SMEM_BYTES);

    // 1) pack weights / biases / frac-diff weights, zero h_0, reset barrier
    prep_kernel<<<1280, 256>>>(Wi, bi, Wo, bo, Wc, bc, dv);
    // 2) x-projection: [T*B,128] @ [128,1536] + bias  -> g_XP
    gemm_bias<<<dim3((T_ * B_) / 64, N3 / 64), 256>>>(inputs, pWxP, pBn, pXP, N3, I_);
    // 3) serial recurrence (persistent, grid-barriered)
    recurrent_kernel<<<NCTA, 256, SMEM_BYTES>>>(out);
    // 4) outputs: [T*B,512] @ [512,128] + bias -> d_out[0 : T*B*O)
    gemm_bias<<<dim3((T_ * B_) / 64, O_ / 64), 256>>>(pHall + B_ * H_, Wout, bout, out, O_, H_);
}

// round 5
// speedup vs baseline: 1.3388x; 1.3388x over previous
#include <cuda_runtime.h>
#include <cuda_bf16.h>
#include <math.h>

#define T_ 512
#define B_ 64
#define I_ 128
#define H_ 512
#define O_ 128
#define K_ 32
#define N3 1536
#define IH 640
#define NCTA 128

typedef unsigned long long u64;

// ---------------- device scratch (allocation-free rule) ----------------
__device__ float g_XP[(size_t)T_ * B_ * N3];           // x-projection + bias  [t][b][h*3+g]
__device__ float g_Hall[(size_t)(T_ + 1) * B_ * H_];   // h_0..h_T  [t][b][h]   (for output GEMM)
__device__ float g_HallT[(size_t)(T_ + 1) * H_ * B_];  // h_0..h_T  [t][h][b]   (for staging)
__device__ float g_WxP[I_ * N3];                       // [k][h*3+g]
__device__ float g_WhP[H_ * N3];                       // [ng][k 512][hloc*3+g]  (32*512*48)
__device__ float g_bn[N3];                             // [h*3+g]
__device__ float g_wd[K_ * H_];                        // [j][h], oldest lag first
__device__ unsigned g_count;
__device__ unsigned g_gen;

// ---------------- f32x2 helpers ----------------
__device__ __forceinline__ void fma2(u64 &d, u64 a, u64 b) {
    asm("fma.rn.f32x2 %0, %1, %2, %0;" : "+l"(d) : "l"(a), "l"(b));
}
__device__ __forceinline__ u64 dup2(float w) {
    u64 r; asm("mov.b64 %0, {%1, %1};" : "=l"(r) : "f"(w)); return r;
}
__device__ __forceinline__ float2 unpack2(u64 v) {
    float2 f; asm("mov.b64 {%0, %1}, %2;" : "=f"(f.x), "=f"(f.y) : "l"(v)); return f;
}
__device__ __forceinline__ float sigmoidf_(float x) { return 1.f / (1.f + expf(-x)); }

// ---------------- prep ----------------
__global__ void prep_kernel(const float *__restrict__ Wi, const float *__restrict__ bi,
                            const float *__restrict__ Wo, const float *__restrict__ bo,
                            const float *__restrict__ Wc, const float *__restrict__ bc,
                            const float *__restrict__ dv) {
    int idx = blockIdx.x * blockDim.x + threadIdx.x;
    if (idx == 0) { g_count = 0u; g_gen = 0u; }
    if (idx < IH * H_) {
        int k = idx >> 9, h = idx & 511;
        float wi = Wi[idx], wo = Wo[idx], wc = Wc[idx];
        if (k < I_) {
            float *p = g_WxP + (size_t)k * N3 + h * 3;
            p[0] = wi; p[1] = wo; p[2] = wc;
        } else {
            int kk = k - I_;
            float *p = g_WhP + (size_t)(h >> 4) * (512 * 48) + (size_t)kk * 48 + (h & 15) * 3;
            p[0] = wi; p[1] = wo; p[2] = wc;
        }
    }
    if (idx < H_) {
        g_bn[idx * 3 + 0] = bi[idx];
        g_bn[idx * 3 + 1] = bo[idx];
        g_bn[idx * 3 + 2] = bc[idx];
        float d = 0.5f * sigmoidf_(dv[idx]);
        float v = 1.f;
        for (int i = 0; i < K_; i++) {          // v_{i+1} = v_i*(i-d)/(i+1); wd[K-1-i]=v_{i+1}
            v *= ((float)i - d) / ((float)i + 1.f);
            g_wd[(K_ - 1 - i) * H_ + idx] = v;
        }
    }
    if (idx < B_ * H_) g_HallT[idx] = 0.f;      // h_0 = 0 (transposed layout used by staging)
}

// ---------------- fp32 GEMM + bias: C[M,N] = A[M,Kd] @ Bm[Kd,N] + bias[N] --------------
// BM=128 BN=64 BK=16, 256 threads, 8m x 4n micro-tile via f32x2 over m-pairs,
// register double-buffered gmem loads, conflict-free As (row stride 130).
__global__ void __launch_bounds__(256) gemm_bias(const float *__restrict__ A,
                                                 const float *__restrict__ Bm,
                                                 const float *__restrict__ bias,
                                                 float *__restrict__ C, int N, int Kd) {
    __shared__ float As[16 * 130];  // [k][m], padded rows
    __shared__ u64   Bs[16 * 64];   // [k][n], dup'd
    int tid = threadIdx.x;
    int m0 = blockIdx.x * 128, n0 = blockIdx.y * 64;
    int tx = tid & 15, ty = tid >> 4;
    int ar = tid >> 1, ac = (tid & 1) * 8;
    int bk = tid >> 4, bn = (tid & 15) * 4;

    u64 acc[4][4];
#pragma unroll
    for (int p = 0; p < 4; p++)
#pragma unroll
        for (int i = 0; i < 4; i++) acc[p][i] = 0ull;

    const float *Arow = A + (size_t)(m0 + ar) * Kd + ac;
    const float *Brow = Bm + (size_t)bk * N + n0 + bn;
    float4 av0 = *(const float4 *)(Arow);
    float4 av1 = *(const float4 *)(Arow + 4);
    float4 bv  = *(const float4 *)(Brow);

    for (int kc = 0; kc < Kd; kc += 16) {
        __syncthreads();
        {
            float a0s[4] = {av0.x, av0.y, av0.z, av0.w};
            float a1s[4] = {av1.x, av1.y, av1.z, av1.w};
#pragma unroll
            for (int q = 0; q < 4; q++) As[(ac + q) * 130 + ar] = a0s[q];
#pragma unroll
            for (int q = 0; q < 4; q++) As[(ac + 4 + q) * 130 + ar] = a1s[q];
            float bvs[4] = {bv.x, bv.y, bv.z, bv.w};
#pragma unroll
            for (int q = 0; q < 4; q++) Bs[bk * 64 + bn + q] = dup2(bvs[q]);
        }
        __syncthreads();
        if (kc + 16 < Kd) {
            av0 = *(const float4 *)(Arow + kc + 16);
            av1 = *(const float4 *)(Arow + kc + 20);
            bv  = *(const float4 *)(Brow + (size_t)(kc + 16) * N);
        }
#pragma unroll
        for (int kk = 0; kk < 16; kk++) {
            u64 a0 = *(const u64 *)&As[kk * 130 + ty * 8 + 0];
            u64 a1 = *(const u64 *)&As[kk * 130 + ty * 8 + 2];
            u64 a2 = *(const u64 *)&As[kk * 130 + ty * 8 + 4];
            u64 a3 = *(const u64 *)&As[kk * 130 + ty * 8 + 6];
            u64 b0 = Bs[kk * 64 + tx],      b1 = Bs[kk * 64 + tx + 16];
            u64 b2 = Bs[kk * 64 + tx + 32], b3 = Bs[kk * 64 + tx + 48];
            fma2(acc[0][0], a0, b0); fma2(acc[0][1], a0, b1);
            fma2(acc[0][2], a0, b2); fma2(acc[0][3], a0, b3);
            fma2(acc[1][0], a1, b0); fma2(acc[1][1], a1, b1);
            fma2(acc[1][2], a1, b2); fma2(acc[1][3], a1, b3);
            fma2(acc[2][0], a2, b0); fma2(acc[2][1], a2, b1);
            fma2(acc[2][2], a2, b2); fma2(acc[2][3], a2, b3);
            fma2(acc[3][0], a3, b0); fma2(acc[3][1], a3, b1);
            fma2(acc[3][2], a3, b2); fma2(acc[3][3], a3, b3);
        }
    }
#pragma unroll
    for (int p = 0; p < 4; p++) {
        int m = m0 + ty * 8 + p * 2;
#pragma unroll
        for (int i = 0; i < 4; i++) {
            int n = n0 + tx + 16 * i;
            float2 v = unpack2(acc[p][i]);
            float bb = bias[n];
            C[(size_t)m * N + n] = v.x + bb;
            C[(size_t)(m + 1) * N + n] = v.y + bb;
        }
    }
}

// ---------------- persistent recurrent kernel: 128 CTAs = 4 bg x 32 ng ----------------
// SMEM floats: Whs[0,24576)  h2s[24576,33792) (512x9 u64)  ring[33792,41984)
//              red[41984,48128) (3072 u64)  wds[48128,48640)
#define SMEM_FLOATS 48640
#define SMEM_BYTES (SMEM_FLOATS * 4)

__global__ void __launch_bounds__(256, 1) recurrent_kernel(float *__restrict__ dout) {
    extern __shared__ float sm[];
    float *Whs = sm;
    u64 *h2s = (u64 *)(sm + 24576);
    float *ring = sm + 33792;
    u64 *red = (u64 *)(sm + 41984);
    const float *redf = sm + 41984;
    float *wds = sm + 48128;

    int tid = threadIdx.x;
    int bid = blockIdx.x;
    int bg = bid >> 5, ng = bid & 31;
    int bbase = bg * 16, hbase = ng * 16;

    // load weight slice [512][48] (coalesced float4)
    {
        const float4 *src = (const float4 *)(g_WhP + (size_t)ng * (512 * 48));
        float4 *dst = (float4 *)Whs;
        for (int i = tid; i < 512 * 48 / 4; i += 256) dst[i] = src[i];
    }
    for (int i = tid; i < K_ * 16; i += 256)
        wds[i] = g_wd[(i >> 4) * H_ + hbase + (i & 15)];
    for (int i = tid; i < K_ * 256; i += 256) ring[i] = 0.f;
    __syncthreads();

    // GEMM role
    int ks = tid >> 5, lane = tid & 31;
    int bpH = lane >> 4, hq = lane & 15;
    int kbase = ks * 64;
    // elementwise role
    int h_l = tid & 15, b_l = tid >> 4;
    int bp = b_l >> 1, comp = b_l & 1;

    unsigned *pcount = &g_count;
    unsigned *pgen = &g_gen;

    for (int t = 0; t < T_; t++) {
        // prefetch x-projection for this thread's (b,h)  (consumed after GEMM)
        const float *xpp = g_XP + ((size_t)t * B_ + bbase + b_l) * N3 + (size_t)(hbase + h_l) * 3;
        float xp0 = xpp[0], xp1 = xpp[1], xp2 = xpp[2];

        // stage h_t slice: g_HallT[t][k 0..511][bbase..bbase+15] -> h2s[k][8 u64]
        {
            const u64 *srcT = (const u64 *)g_HallT + (size_t)t * (H_ * B_ / 2) + bg * 8;
#pragma unroll
            for (int it = 0; it < 16; it++) {
                int idx = tid + it * 256;
                int k = idx >> 3, col = idx & 7;
                h2s[k * 9 + col] = srcT[(size_t)k * 32 + col];
            }
        }
        __syncthreads();

        // GEMM partials: k in [kbase,kbase+64), outputs (4 bp, 1 h, 3 gates)
        u64 a00 = 0, a01 = 0, a02 = 0, a10 = 0, a11 = 0, a12 = 0;
        u64 a20 = 0, a21 = 0, a22 = 0, a30 = 0, a31 = 0, a32 = 0;
        {
            const u64 *hr = h2s + (size_t)kbase * 9 + bpH * 4;
            const float *wr = Whs + kbase * 48 + hq * 3;
#pragma unroll 4
            for (int k = 0; k < 64; k++) {
                u64 h0 = hr[0], h1 = hr[1], h2v = hr[2], h3v = hr[3];
                u64 w0 = dup2(wr[0]), w1 = dup2(wr[1]), w2 = dup2(wr[2]);
                fma2(a00, h0, w0);  fma2(a01, h0, w1);  fma2(a02, h0, w2);
                fma2(a10, h1, w0);  fma2(a11, h1, w1);  fma2(a12, h1, w2);
                fma2(a20, h2v, w0); fma2(a21, h2v, w1); fma2(a22, h2v, w2);
                fma2(a30, h3v, w0); fma2(a31, h3v, w1); fma2(a32, h3v, w2);
                hr += 9; wr += 48;
            }
        }
        {
            u64 *rp = red + ((size_t)(ks * 8 + bpH * 4) * 16 + hq) * 3;
            rp[0] = a00;  rp[1] = a01;  rp[2] = a02;
            rp[48] = a10; rp[49] = a11; rp[50] = a12;
            rp[96] = a20; rp[97] = a21; rp[98] = a22;
            rp[144] = a30; rp[145] = a31; rp[146] = a32;
        }
        __syncthreads();

        // elementwise per (b_l,h_l): reduce k-splits, gates, frac-diff, update
        float p0 = xp0, p1 = xp1, p2 = xp2;
#pragma unroll
        for (int s = 0; s < 8; s++) {
            int base = (((s * 8 + bp) * 16 + h_l) * 3) * 2 + comp;
            p0 += redf[base];
            p1 += redf[base + 2];
            p2 += redf[base + 4];
        }
        float gi = sigmoidf_(p0);
        float go = sigmoidf_(p1);
        float gc = tanhf(p2);
        float conv = 0.f;
        int rbase = b_l * 16 + h_l;
#pragma unroll
        for (int j = 0; j < K_; j++)
            conv += wds[j * 16 + h_l] * ring[(((t + j) & 31) << 8) + rbase];
        float c = gi * gc - conv;
        ring[((t & 31) << 8) + rbase] = c;   // only this thread reads/writes this slot
        float hn = go * tanhf(c);
        g_HallT[((size_t)(t + 1) * H_ + hbase + h_l) * B_ + bbase + b_l] = hn;
        g_Hall[((size_t)(t + 1) * B_ + bbase + b_l) * H_ + hbase + h_l] = hn;
        if (t == T_ - 1)
            dout[(size_t)T_ * B_ * O_ + (size_t)(bbase + b_l) * H_ + hbase + h_l] = hn;

        // ---- grid barrier: acq_rel counter + release/acquire generation word ----
        __syncthreads();
        if (tid == 0) {
            unsigned arrived;
            asm volatile("atom.acq_rel.gpu.global.add.u32 %0, [%1], %2;"
                         : "=r"(arrived) : "l"(pcount), "r"(1u) : "memory");
            arrived += 1u;
            unsigned target = (unsigned)(NCTA * (t + 1));
            if (arrived == target) {
                asm volatile("st.release.gpu.global.u32 [%0], %1;"
                             :: "l"(pgen), "r"((unsigned)(t + 1)) : "memory");
            } else {
                unsigned g;
                do {
                    asm volatile("ld.acquire.gpu.global.u32 %0, [%1];"
                                 : "=r"(g) : "l"(pgen) : "memory");
                } while (g < (unsigned)(t + 1));
            }
        }
        __syncthreads();
    }

    // epilogue: hc_last = ring (slot j == hc_last[j] since 480 % 32 == 0)
    {
        const size_t HC0 = (size_t)T_ * B_ * O_ + (size_t)B_ * H_;
#pragma unroll
        for (int j = 0; j < K_; j++)
            dout[HC0 + ((size_t)j * B_ + bbase + b_l) * H_ + hbase + h_l] =
                ring[(j << 8) + b_l * 16 + h_l];
    }
}

// ---------------- launch ----------------
extern "C" void kernel_launch(void* const* d_in, const int* in_sizes, int n_in,
                              void* d_out, int out_size) {
    const float *inputs = (const float *)d_in[0];
    const float *Wi = (const float *)d_in[1];
    const float *bi = (const float *)d_in[2];
    const float *Wo = (const float *)d_in[3];
    const float *bo = (const float *)d_in[4];
    const float *Wc = (const float *)d_in[5];
    const float *bc = (const float *)d_in[6];
    const float *Wout = (const float *)d_in[7];
    const float *bout = (const float *)d_in[8];
    const float *dv = (const float *)d_in[9];
    float *out = (float *)d_out;

    float *pXP = nullptr, *pHall = nullptr, *pWxP = nullptr, *pBn = nullptr;
    cudaGetSymbolAddress((void **)&pXP, g_XP);
    cudaGetSymbolAddress((void **)&pHall, g_Hall);
    cudaGetSymbolAddress((void **)&pWxP, g_WxP);
    cudaGetSymbolAddress((void **)&pBn, g_bn);
    cudaFuncSetAttribute(recurrent_kernel, cudaFuncAttributeMaxDynamicSharedMemorySize,
                         SMEM_BYTES);

    // 1) pack weights / biases / frac-diff weights, zero h_0 (transposed), reset barrier
    prep_kernel<<<1280, 256>>>(Wi, bi, Wo, bo, Wc, bc, dv);
    // 2) x-projection: [T*B,128] @ [128,1536] + bias  -> g_XP
    gemm_bias<<<dim3((T_ * B_) / 128, N3 / 64), 256>>>(inputs, pWxP, pBn, pXP, N3, I_);
    // 3) serial recurrence (persistent, grid-barriered)
    recurrent_kernel<<<NCTA, 256, SMEM_BYTES>>>(out);
    // 4) outputs: [T*B,512] @ [512,128] + bias -> d_out[0 : T*B*O)
    gemm_bias<<<dim3((T_ * B_) / 128, O_ / 64), 256>>>(pHall + B_ * H_, Wout, bout, out, O_, H_);
}